// round 3
// baseline (speedup 1.0000x reference)
#include <cuda_runtime.h>
#include <math.h>

#define N_NODES 4096
#define F_IN    256
#define F_OUT   512
#define HEADS   8
#define DH      64
#define LOG2E   1.4426950408889634f

typedef unsigned long long u64;

__device__ __forceinline__ u64 dup2(float v) {
    u64 r; asm("mov.b64 %0, {%1, %1};" : "=l"(r) : "f"(v)); return r;
}
__device__ __forceinline__ u64 pk2(float lo, float hi) {
    u64 r; asm("mov.b64 %0, {%1, %2};" : "=l"(r) : "f"(lo), "f"(hi)); return r;
}
__device__ __forceinline__ void unp2(u64 v, float& lo, float& hi) {
    asm("mov.b64 {%0, %1}, %2;" : "=f"(lo), "=f"(hi) : "l"(v));
}
__device__ __forceinline__ void fma2(u64& d, u64 a, u64 b) {
    asm("fma.rn.f32x2 %0, %1, %2, %0;" : "+l"(d) : "l"(a), "l"(b));
}
__device__ __forceinline__ u64 mul2(u64 a, u64 b) {
    u64 r; asm("mul.rn.f32x2 %0, %1, %2;" : "=l"(r) : "l"(a), "l"(b)); return r;
}
__device__ __forceinline__ float ex2f(float x) {
    float y; asm("ex2.approx.ftz.f32 %0, %1;" : "=f"(y) : "f"(x)); return y;
}

// Scratch (no allocations allowed): h = x@W^T, q = h@A  (8 MB each)
__device__ float g_h[N_NODES * F_OUT];
__device__ float g_q[N_NODES * F_OUT];

// ---------------------------------------------------------------------------
// Kernel 1: h[n][o] = sum_k x[n][k] * W[o][k]
// ---------------------------------------------------------------------------
__global__ __launch_bounds__(256) void k_gemm_xwT(const float* __restrict__ X,
                                                  const float* __restrict__ W) {
    __shared__ float sX[16][68];
    __shared__ float sW[16][68];
    const int tid = threadIdx.x;
    const int ty = tid >> 4, tx = tid & 15;
    const int m0 = blockIdx.x * 64, n0 = blockIdx.y * 64;

    float acc[4][4] = {};
    for (int k0 = 0; k0 < F_IN; k0 += 16) {
        {
            const int r  = tid >> 2;
            const int kk = (tid & 3) * 4;
            float4 v = *(const float4*)&X[(m0 + r) * F_IN + k0 + kk];
            sX[kk + 0][r] = v.x; sX[kk + 1][r] = v.y;
            sX[kk + 2][r] = v.z; sX[kk + 3][r] = v.w;
            float4 w = *(const float4*)&W[(n0 + r) * F_IN + k0 + kk];
            sW[kk + 0][r] = w.x; sW[kk + 1][r] = w.y;
            sW[kk + 2][r] = w.z; sW[kk + 3][r] = w.w;
        }
        __syncthreads();
        #pragma unroll
        for (int kk = 0; kk < 16; kk++) {
            float a[4], b[4];
            #pragma unroll
            for (int i = 0; i < 4; i++) a[i] = sX[kk][ty * 4 + i];
            #pragma unroll
            for (int j = 0; j < 4; j++) b[j] = sW[kk][tx * 4 + j];
            #pragma unroll
            for (int i = 0; i < 4; i++)
                #pragma unroll
                for (int j = 0; j < 4; j++)
                    acc[i][j] = fmaf(a[i], b[j], acc[i][j]);
        }
        __syncthreads();
    }
    #pragma unroll
    for (int i = 0; i < 4; i++) {
        float4 v = make_float4(acc[i][0], acc[i][1], acc[i][2], acc[i][3]);
        *(float4*)&g_h[(m0 + ty * 4 + i) * F_OUT + n0 + tx * 4] = v;
    }
}

// ---------------------------------------------------------------------------
// Kernel 2: q[n][h*64+e] = sum_d h[n][h*64+d] * A[h][d][e]
// ---------------------------------------------------------------------------
__global__ __launch_bounds__(256) void k_gemm_hA(const float* __restrict__ A) {
    __shared__ float sH[64][65];
    __shared__ float sA[64][65];
    const int tid = threadIdx.x;
    const int ty = tid >> 4, tx = tid & 15;
    const int head = blockIdx.y;
    const int n0 = blockIdx.x * 64;

    {
        const int r  = tid >> 2;
        const int c0 = (tid & 3) * 16;
        #pragma unroll
        for (int cc = 0; cc < 16; cc += 4) {
            float4 v = *(const float4*)&g_h[(n0 + r) * F_OUT + head * DH + c0 + cc];
            sH[c0 + cc + 0][r] = v.x; sH[c0 + cc + 1][r] = v.y;
            sH[c0 + cc + 2][r] = v.z; sH[c0 + cc + 3][r] = v.w;
            float4 a = *(const float4*)&A[head * DH * DH + r * DH + c0 + cc];
            sA[r][c0 + cc + 0] = a.x; sA[r][c0 + cc + 1] = a.y;
            sA[r][c0 + cc + 2] = a.z; sA[r][c0 + cc + 3] = a.w;
        }
    }
    __syncthreads();

    float acc[4][4] = {};
    #pragma unroll 16
    for (int d = 0; d < DH; d++) {
        float a[4], b[4];
        #pragma unroll
        for (int i = 0; i < 4; i++) a[i] = sH[d][ty * 4 + i];
        #pragma unroll
        for (int j = 0; j < 4; j++) b[j] = sA[d][tx * 4 + j];
        #pragma unroll
        for (int i = 0; i < 4; i++)
            #pragma unroll
            for (int j = 0; j < 4; j++)
                acc[i][j] = fmaf(a[i], b[j], acc[i][j]);
    }
    #pragma unroll
    for (int i = 0; i < 4; i++) {
        float4 v = make_float4(acc[i][0], acc[i][1], acc[i][2], acc[i][3]);
        *(float4*)&g_q[(n0 + ty * 4 + i) * F_OUT + head * DH + tx * 4] = v;
    }
}

// ---------------------------------------------------------------------------
// Kernel 3: fused flash attention, f32x2 packed math.
// Block: 128 threads (tx=tid&7 over keys/dims, ty=tid>>3 over queries).
// Tile: 64 q x 64 keys. Micro-tile per thread: 4 q x 8 keys (S), 4 q x 8 dims (O).
// smem: sQt[d][q] (Q^T * log2e), sK[key][d], sKtP = K^T during S, P after.
// P stored with 16B-chunk XOR swizzle: chunk' = c4 ^ ((q&3)<<2 | (q>>2)&3)
// so stride-64 column reads are bank-conflict-free.
// ---------------------------------------------------------------------------
__global__ __launch_bounds__(128, 4) void k_attn(float* __restrict__ Out) {
    __shared__ float sQt [64 * 64];
    __shared__ float sK  [64 * 64];
    __shared__ float sKtP[64 * 64];

    const int tid  = threadIdx.x;
    const int tx   = tid & 7;     // 0..7  (keys / dims)
    const int ty   = tid >> 3;    // 0..15 (queries)
    const int head = blockIdx.y;
    const int q0   = blockIdx.x * 64;

    // Load Q tile, transpose to d-major, pre-scale by log2(e)
    {
        const int r  = tid >> 1;
        const int h2 = tid & 1;
        const float4* src = (const float4*)&g_q[(q0 + r) * F_OUT + head * DH + h2 * 32];
        #pragma unroll
        for (int u = 0; u < 8; u++) {
            float4 v = src[u];
            const int d = h2 * 32 + u * 4;
            sQt[(d + 0) * 64 + r] = v.x * LOG2E;
            sQt[(d + 1) * 64 + r] = v.y * LOG2E;
            sQt[(d + 2) * 64 + r] = v.z * LOG2E;
            sQt[(d + 3) * 64 + r] = v.w * LOG2E;
        }
    }

    u64 acc2[4][4];
    #pragma unroll
    for (int i = 0; i < 4; i++)
        #pragma unroll
        for (int j = 0; j < 4; j++) acc2[i][j] = 0ull;
    float mrow[4], lrow[4];
    #pragma unroll
    for (int i = 0; i < 4; i++) { mrow[i] = -1.0e30f; lrow[i] = 0.f; }

    for (int key0 = 0; key0 < N_NODES; key0 += 64) {
        __syncthreads();  // (A) prev PV readers done; safe to overwrite sK / sKtP

        // Load K tile: row-major into sK, transposed into sKtP (as K^T)
        {
            const int r  = tid >> 1;
            const int h2 = tid & 1;
            const float4* src = (const float4*)&g_h[(key0 + r) * F_OUT + head * DH + h2 * 32];
            #pragma unroll
            for (int u = 0; u < 8; u++) {
                float4 v = src[u];
                const int d = h2 * 32 + u * 4;
                *(float4*)&sK[r * 64 + d] = v;
                sKtP[(d + 0) * 64 + r] = v.x;
                sKtP[(d + 1) * 64 + r] = v.y;
                sKtP[(d + 2) * 64 + r] = v.z;
                sKtP[(d + 3) * 64 + r] = v.w;
            }
        }
        __syncthreads();  // (B) tiles ready

        // ---- S = (log2e * Q) K^T : packed over key pairs ----
        u64 s2[4][4];
        #pragma unroll
        for (int i = 0; i < 4; i++)
            #pragma unroll
            for (int j = 0; j < 4; j++) s2[i][j] = 0ull;

        #pragma unroll 8
        for (int k = 0; k < DH; k++) {
            float4 aq = *(const float4*)&sQt[k * 64 + ty * 4];
            u64 a0 = dup2(aq.x), a1 = dup2(aq.y), a2 = dup2(aq.z), a3 = dup2(aq.w);
            ulonglong2 b01 = *(const ulonglong2*)&sKtP[k * 64 + tx * 8];
            ulonglong2 b23 = *(const ulonglong2*)&sKtP[k * 64 + tx * 8 + 4];
            fma2(s2[0][0], a0, b01.x); fma2(s2[0][1], a0, b01.y);
            fma2(s2[0][2], a0, b23.x); fma2(s2[0][3], a0, b23.y);
            fma2(s2[1][0], a1, b01.x); fma2(s2[1][1], a1, b01.y);
            fma2(s2[1][2], a1, b23.x); fma2(s2[1][3], a1, b23.y);
            fma2(s2[2][0], a2, b01.x); fma2(s2[2][1], a2, b01.y);
            fma2(s2[2][2], a2, b23.x); fma2(s2[2][3], a2, b23.y);
            fma2(s2[3][0], a3, b01.x); fma2(s2[3][1], a3, b01.y);
            fma2(s2[3][2], a3, b23.x); fma2(s2[3][3], a3, b23.y);
        }

        // ---- LeakyReLU + online softmax (base-2 domain) ----
        #pragma unroll
        for (int i = 0; i < 4; i++) {
            float f[8];
            #pragma unroll
            for (int jj = 0; jj < 4; jj++) unp2(s2[i][jj], f[2 * jj], f[2 * jj + 1]);
            #pragma unroll
            for (int j = 0; j < 8; j++) f[j] = fmaxf(f[j], 0.2f * f[j]);  // LeakyReLU

            float tm = f[0];
            #pragma unroll
            for (int j = 1; j < 8; j++) tm = fmaxf(tm, f[j]);
            tm = fmaxf(tm, __shfl_xor_sync(0xffffffffu, tm, 1));
            tm = fmaxf(tm, __shfl_xor_sync(0xffffffffu, tm, 2));
            tm = fmaxf(tm, __shfl_xor_sync(0xffffffffu, tm, 4));

            const float mnew  = fmaxf(mrow[i], tm);
            const float scale = ex2f(mrow[i] - mnew);
            mrow[i] = mnew;

            float rsum = 0.f;
            #pragma unroll
            for (int j = 0; j < 8; j++) { f[j] = ex2f(f[j] - mnew); rsum += f[j]; }
            rsum += __shfl_xor_sync(0xffffffffu, rsum, 1);
            rsum += __shfl_xor_sync(0xffffffffu, rsum, 2);
            rsum += __shfl_xor_sync(0xffffffffu, rsum, 4);

            lrow[i] = lrow[i] * scale + rsum;
            const u64 sc2 = dup2(scale);
            #pragma unroll
            for (int j = 0; j < 4; j++) acc2[i][j] = mul2(acc2[i][j], sc2);
            #pragma unroll
            for (int jj = 0; jj < 4; jj++) s2[i][jj] = pk2(f[2 * jj], f[2 * jj + 1]);
        }

        __syncthreads();  // (C) all S reads of sKtP done -> overwrite with P

        // ---- store P (swizzled 16B chunks) ----
        #pragma unroll
        for (int i = 0; i < 4; i++) {
            const int swz  = (i << 2) | ty % 4;  // bit-swapped (q&15): q=ty*4+i
            const int base = (ty * 4 + i) * 64;
            ulonglong2 c0; c0.x = s2[i][0]; c0.y = s2[i][1];
            ulonglong2 c1; c1.x = s2[i][2]; c1.y = s2[i][3];
            *(ulonglong2*)&sKtP[base + (((2 * tx + 0) ^ swz) << 2)] = c0;
            *(ulonglong2*)&sKtP[base + (((2 * tx + 1) ^ swz) << 2)] = c1;
        }
        __syncthreads();  // (D) P visible

        // ---- O += P * V  (V = sK) ----
        #pragma unroll 2
        for (int c4 = 0; c4 < 16; c4++) {
            int pb[4];
            #pragma unroll
            for (int i = 0; i < 4; i++)
                pb[i] = (ty * 4 + i) * 64 + ((c4 ^ ((i << 2) | (ty % 4))) << 2);
            #pragma unroll
            for (int cm = 0; cm < 4; cm++) {
                const int c = c4 * 4 + cm;
                u64 p0 = dup2(sKtP[pb[0] + cm]);
                u64 p1 = dup2(sKtP[pb[1] + cm]);
                u64 p2 = dup2(sKtP[pb[2] + cm]);
                u64 p3 = dup2(sKtP[pb[3] + cm]);
                ulonglong2 v01 = *(const ulonglong2*)&sK[c * 64 + tx * 8];
                ulonglong2 v23 = *(const ulonglong2*)&sK[c * 64 + tx * 8 + 4];
                fma2(acc2[0][0], p0, v01.x); fma2(acc2[0][1], p0, v01.y);
                fma2(acc2[0][2], p0, v23.x); fma2(acc2[0][3], p0, v23.y);
                fma2(acc2[1][0], p1, v01.x); fma2(acc2[1][1], p1, v01.y);
                fma2(acc2[1][2], p1, v23.x); fma2(acc2[1][3], p1, v23.y);
                fma2(acc2[2][0], p2, v01.x); fma2(acc2[2][1], p2, v01.y);
                fma2(acc2[2][2], p2, v23.x); fma2(acc2[2][3], p2, v23.y);
                fma2(acc2[3][0], p3, v01.x); fma2(acc2[3][1], p3, v01.y);
                fma2(acc2[3][2], p3, v23.x); fma2(acc2[3][3], p3, v23.y);
            }
        }
    }

    // ---- finalize ----
    #pragma unroll
    for (int i = 0; i < 4; i++) {
        const float inv = 1.0f / lrow[i];
        float o[8];
        #pragma unroll
        for (int jj = 0; jj < 4; jj++) unp2(acc2[i][jj], o[2 * jj], o[2 * jj + 1]);
        float4 lo = make_float4(o[0] * inv, o[1] * inv, o[2] * inv, o[3] * inv);
        float4 hi = make_float4(o[4] * inv, o[5] * inv, o[6] * inv, o[7] * inv);
        float* dst = &Out[(q0 + ty * 4 + i) * F_OUT + head * DH + tx * 8];
        *(float4*)dst       = lo;
        *(float4*)(dst + 4) = hi;
    }
}

// ---------------------------------------------------------------------------
extern "C" void kernel_launch(void* const* d_in, const int* in_sizes, int n_in,
                              void* d_out, int out_size) {
    const float* x = (const float*)d_in[0];
    // d_in[1] = adj (int32) — unused by the reference forward
    const float* W = (const float*)d_in[2];
    const float* A = (const float*)d_in[3];
    float* out = (float*)d_out;

    k_gemm_xwT<<<dim3(N_NODES / 64, F_OUT / 64), 256>>>(x, W);
    k_gemm_hA<<<dim3(N_NODES / 64, HEADS), 256>>>(A);
    k_attn<<<dim3(N_NODES / 64, HEADS), 128>>>(out);
}

// round 5
// speedup vs baseline: 3.2212x; 3.2212x over previous
#include <cuda_runtime.h>
#include <cuda_bf16.h>
#include <math.h>
#include <stdint.h>

#define N_NODES 4096
#define F_IN    256
#define F_OUT   512
#define HEADS   8
#define DH      64
#define LOG2E   1.4426950408889634f

#define KTILE   64
#define NT      (N_NODES / KTILE)   // 64 key tiles
#define PITCH   144                 // bytes per 64-bf16 row (16B aligned, conflict-free)
#define STG     (KTILE * PITCH)     // 9216 bytes per array
#define STAGE_SZ (2 * STG)          // Kh + Kl per stage

// ---------------- device scratch (no allocs allowed) ----------------
__device__ __align__(256) float         g_h [N_NODES * F_OUT];
__device__ __align__(256) __nv_bfloat16 g_hh[N_NODES * F_OUT];
__device__ __align__(256) __nv_bfloat16 g_hl[N_NODES * F_OUT];
__device__ __align__(256) __nv_bfloat16 g_qh[N_NODES * F_OUT];
__device__ __align__(256) __nv_bfloat16 g_ql[N_NODES * F_OUT];

// ---------------- helpers ----------------
__device__ __forceinline__ uint32_t smem_u32(const void* p) {
    uint32_t a;
    asm("{ .reg .u64 t; cvta.to.shared.u64 t, %1; cvt.u32.u64 %0, t; }" : "=r"(a) : "l"(p));
    return a;
}
// pack two fp32 -> bf16x2 (a in low half, b in high half)
__device__ __forceinline__ uint32_t bfpk(float a, float b) {
    uint32_t r; asm("cvt.rn.bf16x2.f32 %0, %1, %2;" : "=r"(r) : "f"(b), "f"(a)); return r;
}
// FFMA-pipe exp2 (no MUFU): magic round + deg-5 poly + exponent add
__device__ __forceinline__ float exp2_fast(float x) {
    const float MAGIC = 12582912.0f;        // 1.5 * 2^23
    float fn = x + MAGIC;
    int   n  = __float_as_int(fn);          // low bits hold round(x) (bias bits 0..8 are 0)
    float t  = fn - MAGIC;                  // round(x)
    float f  = x - t;                       // [-0.5, 0.5]
    float p  = 0.0013333558f;
    p = fmaf(p, f, 0.0096181291f);
    p = fmaf(p, f, 0.0555041087f);
    p = fmaf(p, f, 0.2402265070f);
    p = fmaf(p, f, 0.6931471806f);
    p = fmaf(p, f, 1.0f);
    return __int_as_float(__float_as_int(p) + (n << 23));
}
__device__ __forceinline__ void cpa16(uint32_t dst, const void* src) {
    asm volatile("cp.async.cg.shared.global [%0], [%1], 16;" :: "r"(dst), "l"(src) : "memory");
}
#define CP_COMMIT() asm volatile("cp.async.commit_group;" ::: "memory")
#define CP_WAIT0()  asm volatile("cp.async.wait_group 0;" ::: "memory")

__device__ __forceinline__ void ldsm4(uint32_t a, uint32_t& r0, uint32_t& r1,
                                      uint32_t& r2, uint32_t& r3) {
    asm volatile("ldmatrix.sync.aligned.m8n8.x4.shared.b16 {%0,%1,%2,%3}, [%4];"
                 : "=r"(r0), "=r"(r1), "=r"(r2), "=r"(r3) : "r"(a));
}
__device__ __forceinline__ void ldsm4t(uint32_t a, uint32_t& r0, uint32_t& r1,
                                       uint32_t& r2, uint32_t& r3) {
    asm volatile("ldmatrix.sync.aligned.m8n8.x4.trans.shared.b16 {%0,%1,%2,%3}, [%4];"
                 : "=r"(r0), "=r"(r1), "=r"(r2), "=r"(r3) : "r"(a));
}
// D += A(16x16 bf16) * B(16x8 bf16), fp32 accum
__device__ __forceinline__ void mma16816(float* c, const uint32_t* a, uint32_t b0, uint32_t b1) {
    asm volatile(
        "mma.sync.aligned.m16n8k16.row.col.f32.bf16.bf16.f32 "
        "{%0,%1,%2,%3}, {%4,%5,%6,%7}, {%8,%9}, {%0,%1,%2,%3};"
        : "+f"(c[0]), "+f"(c[1]), "+f"(c[2]), "+f"(c[3])
        : "r"(a[0]), "r"(a[1]), "r"(a[2]), "r"(a[3]), "r"(b0), "r"(b1));
}

// ---------------------------------------------------------------------------
// Kernel 1: h = x @ W^T, fp32; epilogue also writes bf16 hi/lo split.
// ---------------------------------------------------------------------------
__global__ __launch_bounds__(256) void k_gemm_xwT(const float* __restrict__ X,
                                                  const float* __restrict__ W) {
    __shared__ float sX[16][68];
    __shared__ float sW[16][68];
    const int tid = threadIdx.x;
    const int ty = tid >> 4, tx = tid & 15;
    const int m0 = blockIdx.x * 64, n0 = blockIdx.y * 64;

    float acc[4][4] = {};
    for (int k0 = 0; k0 < F_IN; k0 += 16) {
        {
            const int r  = tid >> 2;
            const int kk = (tid & 3) * 4;
            float4 v = *(const float4*)&X[(m0 + r) * F_IN + k0 + kk];
            sX[kk + 0][r] = v.x; sX[kk + 1][r] = v.y;
            sX[kk + 2][r] = v.z; sX[kk + 3][r] = v.w;
            float4 w = *(const float4*)&W[(n0 + r) * F_IN + k0 + kk];
            sW[kk + 0][r] = w.x; sW[kk + 1][r] = w.y;
            sW[kk + 2][r] = w.z; sW[kk + 3][r] = w.w;
        }
        __syncthreads();
        #pragma unroll
        for (int kk = 0; kk < 16; kk++) {
            float a[4], b[4];
            #pragma unroll
            for (int i = 0; i < 4; i++) a[i] = sX[kk][ty * 4 + i];
            #pragma unroll
            for (int j = 0; j < 4; j++) b[j] = sW[kk][tx * 4 + j];
            #pragma unroll
            for (int i = 0; i < 4; i++)
                #pragma unroll
                for (int j = 0; j < 4; j++)
                    acc[i][j] = fmaf(a[i], b[j], acc[i][j]);
        }
        __syncthreads();
    }
    #pragma unroll
    for (int i = 0; i < 4; i++) {
        const int idx = (m0 + ty * 4 + i) * F_OUT + n0 + tx * 4;
        *(float4*)&g_h[idx] = make_float4(acc[i][0], acc[i][1], acc[i][2], acc[i][3]);
        #pragma unroll
        for (int jp = 0; jp < 2; jp++) {
            float v0 = acc[i][2 * jp], v1 = acc[i][2 * jp + 1];
            uint32_t hp = bfpk(v0, v1);
            float r0 = v0 - __uint_as_float(hp << 16);
            float r1 = v1 - __uint_as_float(hp & 0xFFFF0000u);
            *(uint32_t*)&g_hh[idx + 2 * jp] = hp;
            *(uint32_t*)&g_hl[idx + 2 * jp] = bfpk(r0, r1);
        }
    }
}

// ---------------------------------------------------------------------------
// Kernel 2: q = h @ A (per head), scaled by log2(e), written as bf16 hi/lo.
// ---------------------------------------------------------------------------
__global__ __launch_bounds__(256) void k_gemm_hA(const float* __restrict__ A) {
    __shared__ float sH[64][65];
    __shared__ float sA[64][65];
    const int tid = threadIdx.x;
    const int ty = tid >> 4, tx = tid & 15;
    const int head = blockIdx.y;
    const int n0 = blockIdx.x * 64;

    {
        const int r  = tid >> 2;
        const int c0 = (tid & 3) * 16;
        #pragma unroll
        for (int cc = 0; cc < 16; cc += 4) {
            float4 v = *(const float4*)&g_h[(n0 + r) * F_OUT + head * DH + c0 + cc];
            sH[c0 + cc + 0][r] = v.x; sH[c0 + cc + 1][r] = v.y;
            sH[c0 + cc + 2][r] = v.z; sH[c0 + cc + 3][r] = v.w;
            float4 a = *(const float4*)&A[head * DH * DH + r * DH + c0 + cc];
            sA[r][c0 + cc + 0] = a.x; sA[r][c0 + cc + 1] = a.y;
            sA[r][c0 + cc + 2] = a.z; sA[r][c0 + cc + 3] = a.w;
        }
    }
    __syncthreads();

    float acc[4][4] = {};
    #pragma unroll 16
    for (int d = 0; d < DH; d++) {
        float a[4], b[4];
        #pragma unroll
        for (int i = 0; i < 4; i++) a[i] = sH[d][ty * 4 + i];
        #pragma unroll
        for (int j = 0; j < 4; j++) b[j] = sA[d][tx * 4 + j];
        #pragma unroll
        for (int i = 0; i < 4; i++)
            #pragma unroll
            for (int j = 0; j < 4; j++)
                acc[i][j] = fmaf(a[i], b[j], acc[i][j]);
    }
    #pragma unroll
    for (int i = 0; i < 4; i++) {
        const int idx = (n0 + ty * 4 + i) * F_OUT + head * DH + tx * 4;
        #pragma unroll
        for (int jp = 0; jp < 2; jp++) {
            float v0 = acc[i][2 * jp] * LOG2E, v1 = acc[i][2 * jp + 1] * LOG2E;
            uint32_t hp = bfpk(v0, v1);
            float r0 = v0 - __uint_as_float(hp << 16);
            float r1 = v1 - __uint_as_float(hp & 0xFFFF0000u);
            *(uint32_t*)&g_qh[idx + 2 * jp] = hp;
            *(uint32_t*)&g_ql[idx + 2 * jp] = bfpk(r0, r1);
        }
    }
}

// ---------------------------------------------------------------------------
// Kernel 3: flash attention via mma.sync (bf16 hi/lo compensated), no-max softmax.
// Block = 128 threads / 4 warps; each warp owns 16 q rows. Q tile 64 x head.
// Loops 64-key tiles; K tile doubles as V. cp.async double-buffered.
// ---------------------------------------------------------------------------
__global__ __launch_bounds__(128) void k_attn(float* __restrict__ Out) {
    __shared__ __align__(16) char smem[2 * STAGE_SZ];   // 36864 B
    const uint32_t sb = smem_u32(smem);

    const int tid  = threadIdx.x;
    const int w    = tid >> 5;
    const int lane = tid & 31;
    const int head = blockIdx.y;
    const int q0   = blockIdx.x * 64;
    const int hb   = head * DH;

    // ldmatrix per-lane address constants
    const int lm = lane >> 3, lr = lane & 7;
    const int sKey = ((lm >> 1) << 3) + lr;   // S-B: key row offset
    const int sD   = (lm & 1) << 3;           // S-B: d col offset
    const int vKey = ((lm & 1) << 3) + lr;    // V-B(trans): key row offset
    const int vD   = (lm >> 1) << 3;          // V-B(trans): dim col offset
    const int qRow = ((lm & 1) << 3) + lr;    // Q-A: row offset within warp's 16
    const int qCol = (lm >> 1) << 3;

    // ---- stage Q (hi at +0, lo at +STG of stage0), read fragments ----
    {
        const int r = tid >> 1, cb = (tid & 1) * 4;
        const uint32_t d0 = sb + r * PITCH + cb * 16;
        const __nv_bfloat16* qh = &g_qh[(size_t)(q0 + r) * F_OUT + hb];
        const __nv_bfloat16* ql = &g_ql[(size_t)(q0 + r) * F_OUT + hb];
        #pragma unroll
        for (int c = 0; c < 4; c++) cpa16(d0 + c * 16, qh + (cb + c) * 8);
        #pragma unroll
        for (int c = 0; c < 4; c++) cpa16(d0 + STG + c * 16, ql + (cb + c) * 8);
    }
    CP_COMMIT();
    CP_WAIT0();
    __syncthreads();

    uint32_t qa[4][4], qb[4][4];   // Q hi / lo A-fragments, k-steps s=0..3
    {
        const uint32_t qbase = sb + (w * 16 + qRow) * PITCH + qCol * 2;
        #pragma unroll
        for (int s = 0; s < 4; s++) {
            ldsm4(qbase + 16 * s * 2,       qa[s][0], qa[s][1], qa[s][2], qa[s][3]);
            ldsm4(qbase + STG + 16 * s * 2, qb[s][0], qb[s][1], qb[s][2], qb[s][3]);
        }
    }
    __syncthreads();

    // ---- prologue: load K tile 0 into stage 0 ----
    {
        const int r = tid >> 1, cb = (tid & 1) * 4;
        const uint32_t d0 = sb + r * PITCH + cb * 16;
        const __nv_bfloat16* kh = &g_hh[(size_t)r * F_OUT + hb];
        const __nv_bfloat16* kl = &g_hl[(size_t)r * F_OUT + hb];
        #pragma unroll
        for (int c = 0; c < 4; c++) cpa16(d0 + c * 16, kh + (cb + c) * 8);
        #pragma unroll
        for (int c = 0; c < 4; c++) cpa16(d0 + STG + c * 16, kl + (cb + c) * 8);
    }
    CP_COMMIT();

    float oc[8][4];
    #pragma unroll
    for (int j = 0; j < 8; j++)
        #pragma unroll
        for (int k = 0; k < 4; k++) oc[j][k] = 0.f;
    float lA = 0.f, lB = 0.f;

    for (int t = 0; t < NT; t++) {
        CP_WAIT0();
        __syncthreads();
        const uint32_t stg = sb + (t & 1) * STAGE_SZ;

        // prefetch next tile into other stage
        if (t + 1 < NT) {
            const int r = tid >> 1, cb = (tid & 1) * 4;
            const uint32_t d0 = sb + ((t + 1) & 1) * STAGE_SZ + r * PITCH + cb * 16;
            const __nv_bfloat16* kh = &g_hh[(size_t)((t + 1) * KTILE + r) * F_OUT + hb];
            const __nv_bfloat16* kl = &g_hl[(size_t)((t + 1) * KTILE + r) * F_OUT + hb];
            #pragma unroll
            for (int c = 0; c < 4; c++) cpa16(d0 + c * 16, kh + (cb + c) * 8);
            #pragma unroll
            for (int c = 0; c < 4; c++) cpa16(d0 + STG + c * 16, kl + (cb + c) * 8);
        }
        CP_COMMIT();

        // ---- S = Q K^T (3-mma compensated) ----
        float sc[8][4];
        #pragma unroll
        for (int j = 0; j < 8; j++)
            #pragma unroll
            for (int k = 0; k < 4; k++) sc[j][k] = 0.f;

        const uint32_t sAddr = stg + sKey * PITCH + sD * 2;
        #pragma unroll
        for (int s = 0; s < 4; s++) {
            #pragma unroll
            for (int u = 0; u < 4; u++) {
                const uint32_t a = sAddr + (16 * u) * PITCH + (16 * s) * 2;
                uint32_t h0, h1, h2, h3, l0, l1, l2, l3;
                ldsm4(a,       h0, h1, h2, h3);
                ldsm4(a + STG, l0, l1, l2, l3);
                mma16816(sc[2 * u],     qa[s], h0, h1);
                mma16816(sc[2 * u + 1], qa[s], h2, h3);
                mma16816(sc[2 * u],     qa[s], l0, l1);
                mma16816(sc[2 * u + 1], qa[s], l2, l3);
                mma16816(sc[2 * u],     qb[s], h0, h1);
                mma16816(sc[2 * u + 1], qb[s], h2, h3);
            }
        }

        // ---- softmax: p = 2^(leaky(s)), build P hi/lo A-frags, accumulate lsum ----
        uint32_t pah[4][4], pal[4][4];
        #pragma unroll
        for (int u = 0; u < 4; u++) {
            float e[8];
            #pragma unroll
            for (int k = 0; k < 4; k++) {
                float v0 = sc[2 * u][k];
                e[k] = exp2_fast(fmaxf(v0, 0.2f * v0));
                float v1 = sc[2 * u + 1][k];
                e[4 + k] = exp2_fast(fmaxf(v1, 0.2f * v1));
            }
            lA += (e[0] + e[1]) + (e[4] + e[5]);
            lB += (e[2] + e[3]) + (e[6] + e[7]);
            #pragma unroll
            for (int k = 0; k < 4; k++) {
                const float f0 = e[2 * (k >> 1) + (k & 1) * 0 + ((k & 2) ? 4 : 0) + 0];
                (void)f0;
            }
            // pah[u] = {rows g (2u), rows g+8 (2u), rows g (2u+1), rows g+8 (2u+1)}
            uint32_t p0 = bfpk(e[0], e[1]);
            uint32_t p1 = bfpk(e[2], e[3]);
            uint32_t p2 = bfpk(e[4], e[5]);
            uint32_t p3 = bfpk(e[6], e[7]);
            pah[u][0] = p0; pah[u][1] = p1; pah[u][2] = p2; pah[u][3] = p3;
            pal[u][0] = bfpk(e[0] - __uint_as_float(p0 << 16),
                             e[1] - __uint_as_float(p0 & 0xFFFF0000u));
            pal[u][1] = bfpk(e[2] - __uint_as_float(p1 << 16),
                             e[3] - __uint_as_float(p1 & 0xFFFF0000u));
            pal[u][2] = bfpk(e[4] - __uint_as_float(p2 << 16),
                             e[5] - __uint_as_float(p2 & 0xFFFF0000u));
            pal[u][3] = bfpk(e[6] - __uint_as_float(p3 << 16),
                             e[7] - __uint_as_float(p3 & 0xFFFF0000u));
        }

        // ---- O += P V (V = K tile; trans ldmatrix; 3-mma compensated) ----
        const uint32_t vAddr = stg + vKey * PITCH + vD * 2;
        #pragma unroll
        for (int s = 0; s < 4; s++) {
            #pragma unroll
            for (int u = 0; u < 4; u++) {
                const uint32_t a = vAddr + (16 * s) * PITCH + (16 * u) * 2;
                uint32_t h0, h1, h2, h3, l0, l1, l2, l3;
                ldsm4t(a,       h0, h1, h2, h3);
                ldsm4t(a + STG, l0, l1, l2, l3);
                mma16816(oc[2 * u],     pah[s], h0, h1);
                mma16816(oc[2 * u + 1], pah[s], h2, h3);
                mma16816(oc[2 * u],     pah[s], l0, l1);
                mma16816(oc[2 * u + 1], pah[s], l2, l3);
                mma16816(oc[2 * u],     pal[s], h0, h1);
                mma16816(oc[2 * u + 1], pal[s], h2, h3);
            }
        }
    }

    // ---- reduce lsum across quad (lanes sharing the same row g) ----
    lA += __shfl_xor_sync(0xffffffffu, lA, 1);
    lA += __shfl_xor_sync(0xffffffffu, lA, 2);
    lB += __shfl_xor_sync(0xffffffffu, lB, 1);
    lB += __shfl_xor_sync(0xffffffffu, lB, 2);
    const float invA = 1.0f / lA, invB = 1.0f / lB;

    // ---- write O ----
    const int g  = lane >> 2, tg = lane & 3;
    const int rowA = q0 + w * 16 + g;
    float* outA = &Out[(size_t)rowA * F_OUT + hb + 2 * tg];
    float* outB = outA + 8 * F_OUT;
    #pragma unroll
    for (int j = 0; j < 8; j++) {
        *(float2*)(outA + 8 * j) = make_float2(oc[j][0] * invA, oc[j][1] * invA);
        *(float2*)(outB + 8 * j) = make_float2(oc[j][2] * invB, oc[j][3] * invB);
    }
}

// ---------------------------------------------------------------------------
extern "C" void kernel_launch(void* const* d_in, const int* in_sizes, int n_in,
                              void* d_out, int out_size) {
    const float* x = (const float*)d_in[0];
    // d_in[1] = adj (unused by the reference forward)
    const float* W = (const float*)d_in[2];
    const float* A = (const float*)d_in[3];
    float* out = (float*)d_out;

    k_gemm_xwT<<<dim3(N_NODES / 64, F_OUT / 64), 256>>>(x, W);
    k_gemm_hA<<<dim3(N_NODES / 64, HEADS), 256>>>(A);
    k_attn<<<dim3(N_NODES / 64, HEADS), 128>>>(out);
}

// round 6
// speedup vs baseline: 4.0272x; 1.2502x over previous
#include <cuda_runtime.h>
#include <cuda_bf16.h>
#include <math.h>
#include <stdint.h>

#define N_NODES 4096
#define F_IN    256
#define F_OUT   512
#define HEADS   8
#define DH      64
#define LOG2E   1.4426950408889634f

#define KTILE   64
#define NT      (N_NODES / KTILE)   // 64 key tiles
#define PITCH   144                 // bytes per 64-bf16 row (16B aligned, conflict-free)
#define STG     (KTILE * PITCH)     // 9216 bytes per array
#define STAGE_SZ (2 * STG)          // Kh + Kl per stage

// ---------------- device scratch (no allocs allowed) ----------------
__device__ __align__(256) float         g_h [N_NODES * F_OUT];
__device__ __align__(256) __nv_bfloat16 g_hh[N_NODES * F_OUT];
__device__ __align__(256) __nv_bfloat16 g_hl[N_NODES * F_OUT];
__device__ __align__(256) __nv_bfloat16 g_qh[N_NODES * F_OUT];
__device__ __align__(256) __nv_bfloat16 g_ql[N_NODES * F_OUT];

// ---------------- helpers ----------------
__device__ __forceinline__ uint32_t smem_u32(const void* p) {
    uint32_t a;
    asm("{ .reg .u64 t; cvta.to.shared.u64 t, %1; cvt.u32.u64 %0, t; }" : "=r"(a) : "l"(p));
    return a;
}
// pack two fp32 -> bf16x2 (a in low half, b in high half)
__device__ __forceinline__ uint32_t bfpk(float a, float b) {
    uint32_t r; asm("cvt.rn.bf16x2.f32 %0, %1, %2;" : "=r"(r) : "f"(b), "f"(a)); return r;
}
// FFMA-pipe exp2 (no MUFU): magic round + deg-5 poly + exponent add
__device__ __forceinline__ float exp2_fast(float x) {
    const float MAGIC = 12582912.0f;        // 1.5 * 2^23
    float fn = x + MAGIC;
    int   n  = __float_as_int(fn);
    float t  = fn - MAGIC;
    float f  = x - t;                       // [-0.5, 0.5]
    float p  = 0.0013333558f;
    p = fmaf(p, f, 0.0096181291f);
    p = fmaf(p, f, 0.0555041087f);
    p = fmaf(p, f, 0.2402265070f);
    p = fmaf(p, f, 0.6931471806f);
    p = fmaf(p, f, 1.0f);
    return __int_as_float(__float_as_int(p) + (n << 23));
}
__device__ __forceinline__ void cpa16(uint32_t dst, const void* src) {
    asm volatile("cp.async.cg.shared.global [%0], [%1], 16;" :: "r"(dst), "l"(src) : "memory");
}
#define CP_COMMIT() asm volatile("cp.async.commit_group;" ::: "memory")
#define CP_WAIT0()  asm volatile("cp.async.wait_group 0;" ::: "memory")

__device__ __forceinline__ void ldsm4(uint32_t a, uint32_t& r0, uint32_t& r1,
                                      uint32_t& r2, uint32_t& r3) {
    asm volatile("ldmatrix.sync.aligned.m8n8.x4.shared.b16 {%0,%1,%2,%3}, [%4];"
                 : "=r"(r0), "=r"(r1), "=r"(r2), "=r"(r3) : "r"(a));
}
__device__ __forceinline__ void ldsm4t(uint32_t a, uint32_t& r0, uint32_t& r1,
                                       uint32_t& r2, uint32_t& r3) {
    asm volatile("ldmatrix.sync.aligned.m8n8.x4.trans.shared.b16 {%0,%1,%2,%3}, [%4];"
                 : "=r"(r0), "=r"(r1), "=r"(r2), "=r"(r3) : "r"(a));
}
// D += A(16x16 bf16) * B(16x8 bf16), fp32 accum
__device__ __forceinline__ void mma16816(float* c, const uint32_t* a, uint32_t b0, uint32_t b1) {
    asm volatile(
        "mma.sync.aligned.m16n8k16.row.col.f32.bf16.bf16.f32 "
        "{%0,%1,%2,%3}, {%4,%5,%6,%7}, {%8,%9}, {%0,%1,%2,%3};"
        : "+f"(c[0]), "+f"(c[1]), "+f"(c[2]), "+f"(c[3])
        : "r"(a[0]), "r"(a[1]), "r"(a[2]), "r"(a[3]), "r"(b0), "r"(b1));
}

// ---------------------------------------------------------------------------
// Kernel 1: h = x @ W^T, fp32; epilogue also writes bf16 hi/lo split.
// ---------------------------------------------------------------------------
__global__ __launch_bounds__(256) void k_gemm_xwT(const float* __restrict__ X,
                                                  const float* __restrict__ W) {
    __shared__ float sX[16][68];
    __shared__ float sW[16][68];
    const int tid = threadIdx.x;
    const int ty = tid >> 4, tx = tid & 15;
    const int m0 = blockIdx.x * 64, n0 = blockIdx.y * 64;

    float acc[4][4] = {};
    for (int k0 = 0; k0 < F_IN; k0 += 16) {
        {
            const int r  = tid >> 2;
            const int kk = (tid & 3) * 4;
            float4 v = *(const float4*)&X[(m0 + r) * F_IN + k0 + kk];
            sX[kk + 0][r] = v.x; sX[kk + 1][r] = v.y;
            sX[kk + 2][r] = v.z; sX[kk + 3][r] = v.w;
            float4 w = *(const float4*)&W[(n0 + r) * F_IN + k0 + kk];
            sW[kk + 0][r] = w.x; sW[kk + 1][r] = w.y;
            sW[kk + 2][r] = w.z; sW[kk + 3][r] = w.w;
        }
        __syncthreads();
        #pragma unroll
        for (int kk = 0; kk < 16; kk++) {
            float a[4], b[4];
            #pragma unroll
            for (int i = 0; i < 4; i++) a[i] = sX[kk][ty * 4 + i];
            #pragma unroll
            for (int j = 0; j < 4; j++) b[j] = sW[kk][tx * 4 + j];
            #pragma unroll
            for (int i = 0; i < 4; i++)
                #pragma unroll
                for (int j = 0; j < 4; j++)
                    acc[i][j] = fmaf(a[i], b[j], acc[i][j]);
        }
        __syncthreads();
    }
    #pragma unroll
    for (int i = 0; i < 4; i++) {
        const int idx = (m0 + ty * 4 + i) * F_OUT + n0 + tx * 4;
        *(float4*)&g_h[idx] = make_float4(acc[i][0], acc[i][1], acc[i][2], acc[i][3]);
        #pragma unroll
        for (int jp = 0; jp < 2; jp++) {
            float v0 = acc[i][2 * jp], v1 = acc[i][2 * jp + 1];
            uint32_t hp = bfpk(v0, v1);
            float r0 = v0 - __uint_as_float(hp << 16);
            float r1 = v1 - __uint_as_float(hp & 0xFFFF0000u);
            *(uint32_t*)&g_hh[idx + 2 * jp] = hp;
            *(uint32_t*)&g_hl[idx + 2 * jp] = bfpk(r0, r1);
        }
    }
}

// ---------------------------------------------------------------------------
// Kernel 2: q = h @ A (per head), scaled by log2(e), written as bf16 hi/lo.
// ---------------------------------------------------------------------------
__global__ __launch_bounds__(256) void k_gemm_hA(const float* __restrict__ A) {
    __shared__ float sH[64][65];
    __shared__ float sA[64][65];
    const int tid = threadIdx.x;
    const int ty = tid >> 4, tx = tid & 15;
    const int head = blockIdx.y;
    const int n0 = blockIdx.x * 64;

    {
        const int r  = tid >> 2;
        const int c0 = (tid & 3) * 16;
        #pragma unroll
        for (int cc = 0; cc < 16; cc += 4) {
            float4 v = *(const float4*)&g_h[(n0 + r) * F_OUT + head * DH + c0 + cc];
            sH[c0 + cc + 0][r] = v.x; sH[c0 + cc + 1][r] = v.y;
            sH[c0 + cc + 2][r] = v.z; sH[c0 + cc + 3][r] = v.w;
            float4 a = *(const float4*)&A[head * DH * DH + r * DH + c0 + cc];
            sA[r][c0 + cc + 0] = a.x; sA[r][c0 + cc + 1] = a.y;
            sA[r][c0 + cc + 2] = a.z; sA[r][c0 + cc + 3] = a.w;
        }
    }
    __syncthreads();

    float acc[4][4] = {};
    #pragma unroll 16
    for (int d = 0; d < DH; d++) {
        float a[4], b[4];
        #pragma unroll
        for (int i = 0; i < 4; i++) a[i] = sH[d][ty * 4 + i];
        #pragma unroll
        for (int j = 0; j < 4; j++) b[j] = sA[d][tx * 4 + j];
        #pragma unroll
        for (int i = 0; i < 4; i++)
            #pragma unroll
            for (int j = 0; j < 4; j++)
                acc[i][j] = fmaf(a[i], b[j], acc[i][j]);
    }
    #pragma unroll
    for (int i = 0; i < 4; i++) {
        const int idx = (n0 + ty * 4 + i) * F_OUT + head * DH + tx * 4;
        #pragma unroll
        for (int jp = 0; jp < 2; jp++) {
            float v0 = acc[i][2 * jp] * LOG2E, v1 = acc[i][2 * jp + 1] * LOG2E;
            uint32_t hp = bfpk(v0, v1);
            float r0 = v0 - __uint_as_float(hp << 16);
            float r1 = v1 - __uint_as_float(hp & 0xFFFF0000u);
            *(uint32_t*)&g_qh[idx + 2 * jp] = hp;
            *(uint32_t*)&g_ql[idx + 2 * jp] = bfpk(r0, r1);
        }
    }
}

// ---------------------------------------------------------------------------
// Kernel 3: flash attention via mma.sync; per-16-key-block fused
// S -> softmax -> PV to minimize live registers (4 blocks/SM, single wave).
// ---------------------------------------------------------------------------
__global__ __launch_bounds__(128, 4) void k_attn(float* __restrict__ Out) {
    __shared__ __align__(16) char smem[2 * STAGE_SZ];   // 36864 B
    const uint32_t sb = smem_u32(smem);

    const int tid  = threadIdx.x;
    const int w    = tid >> 5;
    const int lane = tid & 31;
    const int head = blockIdx.y;
    const int q0   = blockIdx.x * 64;
    const int hb   = head * DH;

    // ldmatrix per-lane address constants
    const int lm = lane >> 3, lr = lane & 7;
    const int sKey = ((lm >> 1) << 3) + lr;   // S-B: key row offset
    const int sD   = (lm & 1) << 3;           // S-B: d col offset
    const int vKey = ((lm & 1) << 3) + lr;    // V-B(trans): key row offset
    const int vD   = (lm >> 1) << 3;          // V-B(trans): dim col offset
    const int qRow = ((lm & 1) << 3) + lr;    // Q-A: row offset within warp's 16
    const int qCol = (lm >> 1) << 3;

    // ---- stage Q (hi at +0, lo at +STG of stage0), read fragments ----
    {
        const int r = tid >> 1, cb = (tid & 1) * 4;
        const uint32_t d0 = sb + r * PITCH + cb * 16;
        const __nv_bfloat16* qh = &g_qh[(size_t)(q0 + r) * F_OUT + hb];
        const __nv_bfloat16* ql = &g_ql[(size_t)(q0 + r) * F_OUT + hb];
        #pragma unroll
        for (int c = 0; c < 4; c++) cpa16(d0 + c * 16, qh + (cb + c) * 8);
        #pragma unroll
        for (int c = 0; c < 4; c++) cpa16(d0 + STG + c * 16, ql + (cb + c) * 8);
    }
    CP_COMMIT();
    CP_WAIT0();
    __syncthreads();

    uint32_t qa[4][4], qb[4][4];   // Q hi / lo A-fragments, k-steps s=0..3
    {
        const uint32_t qbase = sb + (w * 16 + qRow) * PITCH + qCol * 2;
        #pragma unroll
        for (int s = 0; s < 4; s++) {
            ldsm4(qbase + 16 * s * 2,       qa[s][0], qa[s][1], qa[s][2], qa[s][3]);
            ldsm4(qbase + STG + 16 * s * 2, qb[s][0], qb[s][1], qb[s][2], qb[s][3]);
        }
    }
    __syncthreads();

    // ---- prologue: load K tile 0 into stage 0 ----
    {
        const int r = tid >> 1, cb = (tid & 1) * 4;
        const uint32_t d0 = sb + r * PITCH + cb * 16;
        const __nv_bfloat16* kh = &g_hh[(size_t)r * F_OUT + hb];
        const __nv_bfloat16* kl = &g_hl[(size_t)r * F_OUT + hb];
        #pragma unroll
        for (int c = 0; c < 4; c++) cpa16(d0 + c * 16, kh + (cb + c) * 8);
        #pragma unroll
        for (int c = 0; c < 4; c++) cpa16(d0 + STG + c * 16, kl + (cb + c) * 8);
    }
    CP_COMMIT();

    float oc[8][4];
    #pragma unroll
    for (int j = 0; j < 8; j++)
        #pragma unroll
        for (int k = 0; k < 4; k++) oc[j][k] = 0.f;
    float lA = 0.f, lB = 0.f;

    for (int t = 0; t < NT; t++) {
        CP_WAIT0();
        __syncthreads();
        const uint32_t stg = sb + (t & 1) * STAGE_SZ;

        // prefetch next tile into other stage
        if (t + 1 < NT) {
            const int r = tid >> 1, cb = (tid & 1) * 4;
            const uint32_t d0 = sb + ((t + 1) & 1) * STAGE_SZ + r * PITCH + cb * 16;
            const __nv_bfloat16* kh = &g_hh[(size_t)((t + 1) * KTILE + r) * F_OUT + hb];
            const __nv_bfloat16* kl = &g_hl[(size_t)((t + 1) * KTILE + r) * F_OUT + hb];
            #pragma unroll
            for (int c = 0; c < 4; c++) cpa16(d0 + c * 16, kh + (cb + c) * 8);
            #pragma unroll
            for (int c = 0; c < 4; c++) cpa16(d0 + STG + c * 16, kl + (cb + c) * 8);
        }
        CP_COMMIT();

        const uint32_t sAddr = stg + sKey * PITCH + sD * 2;
        const uint32_t vAddr = stg + vKey * PITCH + vD * 2;

        // ---- per-16-key block: S -> softmax -> PV (minimal live registers) ----
        #pragma unroll
        for (int u = 0; u < 4; u++) {
            // S = Q K^T for this key block (3-mma compensated)
            float sc[2][4];
            #pragma unroll
            for (int k = 0; k < 4; k++) { sc[0][k] = 0.f; sc[1][k] = 0.f; }

            #pragma unroll
            for (int s = 0; s < 4; s++) {
                const uint32_t a = sAddr + (16 * u) * PITCH + (16 * s) * 2;
                uint32_t h0, h1, h2, h3, l0, l1, l2, l3;
                ldsm4(a,       h0, h1, h2, h3);
                ldsm4(a + STG, l0, l1, l2, l3);
                mma16816(sc[0], qa[s], h0, h1);
                mma16816(sc[1], qa[s], h2, h3);
                mma16816(sc[0], qa[s], l0, l1);
                mma16816(sc[1], qa[s], l2, l3);
                mma16816(sc[0], qb[s], h0, h1);
                mma16816(sc[1], qb[s], h2, h3);
            }

            // softmax: p = 2^(leaky(s)); build P hi/lo A-frags; accumulate lsum
            float e[8];
            #pragma unroll
            for (int k = 0; k < 4; k++) {
                float v0 = sc[0][k];
                e[k] = exp2_fast(fmaxf(v0, 0.2f * v0));
                float v1 = sc[1][k];
                e[4 + k] = exp2_fast(fmaxf(v1, 0.2f * v1));
            }
            lA += (e[0] + e[1]) + (e[4] + e[5]);
            lB += (e[2] + e[3]) + (e[6] + e[7]);

            uint32_t pah[4], pal[4];
            pah[0] = bfpk(e[0], e[1]);
            pah[1] = bfpk(e[2], e[3]);
            pah[2] = bfpk(e[4], e[5]);
            pah[3] = bfpk(e[6], e[7]);
            pal[0] = bfpk(e[0] - __uint_as_float(pah[0] << 16),
                          e[1] - __uint_as_float(pah[0] & 0xFFFF0000u));
            pal[1] = bfpk(e[2] - __uint_as_float(pah[1] << 16),
                          e[3] - __uint_as_float(pah[1] & 0xFFFF0000u));
            pal[2] = bfpk(e[4] - __uint_as_float(pah[2] << 16),
                          e[5] - __uint_as_float(pah[2] & 0xFFFF0000u));
            pal[3] = bfpk(e[6] - __uint_as_float(pah[3] << 16),
                          e[7] - __uint_as_float(pah[3] & 0xFFFF0000u));

            // O += P V for this key block (V = K tile, trans ldmatrix)
            #pragma unroll
            for (int d = 0; d < 4; d++) {
                const uint32_t a = vAddr + (16 * u) * PITCH + (16 * d) * 2;
                uint32_t h0, h1, h2, h3, l0, l1, l2, l3;
                ldsm4t(a,       h0, h1, h2, h3);
                ldsm4t(a + STG, l0, l1, l2, l3);
                mma16816(oc[2 * d],     pah, h0, h1);
                mma16816(oc[2 * d + 1], pah, h2, h3);
                mma16816(oc[2 * d],     pah, l0, l1);
                mma16816(oc[2 * d + 1], pah, l2, l3);
                mma16816(oc[2 * d],     pal, h0, h1);
                mma16816(oc[2 * d + 1], pal, h2, h3);
            }
        }
    }

    // ---- reduce lsum across quad (lanes sharing the same row g) ----
    lA += __shfl_xor_sync(0xffffffffu, lA, 1);
    lA += __shfl_xor_sync(0xffffffffu, lA, 2);
    lB += __shfl_xor_sync(0xffffffffu, lB, 1);
    lB += __shfl_xor_sync(0xffffffffu, lB, 2);
    const float invA = 1.0f / lA, invB = 1.0f / lB;

    // ---- write O ----
    const int g  = lane >> 2, tg = lane & 3;
    const int rowA = q0 + w * 16 + g;
    float* outA = &Out[(size_t)rowA * F_OUT + hb + 2 * tg];
    float* outB = outA + 8 * F_OUT;
    #pragma unroll
    for (int j = 0; j < 8; j++) {
        *(float2*)(outA + 8 * j) = make_float2(oc[j][0] * invA, oc[j][1] * invA);
        *(float2*)(outB + 8 * j) = make_float2(oc[j][2] * invB, oc[j][3] * invB);
    }
}

// ---------------------------------------------------------------------------
extern "C" void kernel_launch(void* const* d_in, const int* in_sizes, int n_in,
                              void* d_out, int out_size) {
    const float* x = (const float*)d_in[0];
    // d_in[1] = adj (unused by the reference forward)
    const float* W = (const float*)d_in[2];
    const float* A = (const float*)d_in[3];
    float* out = (float*)d_out;

    k_gemm_xwT<<<dim3(N_NODES / 64, F_OUT / 64), 256>>>(x, W);
    k_gemm_hA<<<dim3(N_NODES / 64, HEADS), 256>>>(A);
    k_attn<<<dim3(N_NODES / 64, HEADS), 128>>>(out);
}

// round 7
// speedup vs baseline: 4.2830x; 1.0635x over previous
#include <cuda_runtime.h>
#include <cuda_bf16.h>
#include <math.h>
#include <stdint.h>

#define N_NODES 4096
#define F_IN    256
#define F_OUT   512
#define HEADS   8
#define DH      64
#define LOG2E   1.4426950408889634f

#define KTILE   64
#define NT      (N_NODES / KTILE)   // 64 key tiles
#define QTILE   128                 // q rows per block (32 per warp)
#define PITCH   144                 // bytes per 64-bf16 row (16B aligned, conflict-free)
#define STG     (KTILE * PITCH)     // 9216 bytes per array
#define STAGE_SZ (2 * STG)          // Kh + Kl per stage (18432)

// ---------------- device scratch (no allocs allowed) ----------------
__device__ __align__(256) float         g_h [N_NODES * F_OUT];
__device__ __align__(256) __nv_bfloat16 g_hh[N_NODES * F_OUT];
__device__ __align__(256) __nv_bfloat16 g_hl[N_NODES * F_OUT];
__device__ __align__(256) __nv_bfloat16 g_qh[N_NODES * F_OUT];
__device__ __align__(256) __nv_bfloat16 g_ql[N_NODES * F_OUT];

// ---------------- helpers ----------------
__device__ __forceinline__ uint32_t smem_u32(const void* p) {
    uint32_t a;
    asm("{ .reg .u64 t; cvta.to.shared.u64 t, %1; cvt.u32.u64 %0, t; }" : "=r"(a) : "l"(p));
    return a;
}
__device__ __forceinline__ uint32_t bfpk(float a, float b) {
    uint32_t r; asm("cvt.rn.bf16x2.f32 %0, %1, %2;" : "=r"(r) : "f"(b), "f"(a)); return r;
}
// FFMA-pipe exp2 (no MUFU)
__device__ __forceinline__ float exp2_fast(float x) {
    const float MAGIC = 12582912.0f;        // 1.5 * 2^23
    float fn = x + MAGIC;
    int   n  = __float_as_int(fn);
    float t  = fn - MAGIC;
    float f  = x - t;                       // [-0.5, 0.5]
    float p  = 0.0013333558f;
    p = fmaf(p, f, 0.0096181291f);
    p = fmaf(p, f, 0.0555041087f);
    p = fmaf(p, f, 0.2402265070f);
    p = fmaf(p, f, 0.6931471806f);
    p = fmaf(p, f, 1.0f);
    return __int_as_float(__float_as_int(p) + (n << 23));
}
__device__ __forceinline__ void cpa16(uint32_t dst, const void* src) {
    asm volatile("cp.async.cg.shared.global [%0], [%1], 16;" :: "r"(dst), "l"(src) : "memory");
}
#define CP_COMMIT() asm volatile("cp.async.commit_group;" ::: "memory")
#define CP_WAIT0()  asm volatile("cp.async.wait_group 0;" ::: "memory")

__device__ __forceinline__ void ldsm4(uint32_t a, uint32_t& r0, uint32_t& r1,
                                      uint32_t& r2, uint32_t& r3) {
    asm volatile("ldmatrix.sync.aligned.m8n8.x4.shared.b16 {%0,%1,%2,%3}, [%4];"
                 : "=r"(r0), "=r"(r1), "=r"(r2), "=r"(r3) : "r"(a));
}
__device__ __forceinline__ void ldsm4t(uint32_t a, uint32_t& r0, uint32_t& r1,
                                       uint32_t& r2, uint32_t& r3) {
    asm volatile("ldmatrix.sync.aligned.m8n8.x4.trans.shared.b16 {%0,%1,%2,%3}, [%4];"
                 : "=r"(r0), "=r"(r1), "=r"(r2), "=r"(r3) : "r"(a));
}
__device__ __forceinline__ void mma16816(float* c, const uint32_t* a, uint32_t b0, uint32_t b1) {
    asm volatile(
        "mma.sync.aligned.m16n8k16.row.col.f32.bf16.bf16.f32 "
        "{%0,%1,%2,%3}, {%4,%5,%6,%7}, {%8,%9}, {%0,%1,%2,%3};"
        : "+f"(c[0]), "+f"(c[1]), "+f"(c[2]), "+f"(c[3])
        : "r"(a[0]), "r"(a[1]), "r"(a[2]), "r"(a[3]), "r"(b0), "r"(b1));
}

// ---------------------------------------------------------------------------
// Kernel 1: h = x @ W^T, fp32; epilogue also writes bf16 hi/lo split.
// ---------------------------------------------------------------------------
__global__ __launch_bounds__(256) void k_gemm_xwT(const float* __restrict__ X,
                                                  const float* __restrict__ W) {
    __shared__ float sX[16][68];
    __shared__ float sW[16][68];
    const int tid = threadIdx.x;
    const int ty = tid >> 4, tx = tid & 15;
    const int m0 = blockIdx.x * 64, n0 = blockIdx.y * 64;

    float acc[4][4] = {};
    for (int k0 = 0; k0 < F_IN; k0 += 16) {
        {
            const int r  = tid >> 2;
            const int kk = (tid & 3) * 4;
            float4 v = *(const float4*)&X[(m0 + r) * F_IN + k0 + kk];
            sX[kk + 0][r] = v.x; sX[kk + 1][r] = v.y;
            sX[kk + 2][r] = v.z; sX[kk + 3][r] = v.w;
            float4 w = *(const float4*)&W[(n0 + r) * F_IN + k0 + kk];
            sW[kk + 0][r] = w.x; sW[kk + 1][r] = w.y;
            sW[kk + 2][r] = w.z; sW[kk + 3][r] = w.w;
        }
        __syncthreads();
        #pragma unroll
        for (int kk = 0; kk < 16; kk++) {
            float a[4], b[4];
            #pragma unroll
            for (int i = 0; i < 4; i++) a[i] = sX[kk][ty * 4 + i];
            #pragma unroll
            for (int j = 0; j < 4; j++) b[j] = sW[kk][tx * 4 + j];
            #pragma unroll
            for (int i = 0; i < 4; i++)
                #pragma unroll
                for (int j = 0; j < 4; j++)
                    acc[i][j] = fmaf(a[i], b[j], acc[i][j]);
        }
        __syncthreads();
    }
    #pragma unroll
    for (int i = 0; i < 4; i++) {
        const int idx = (m0 + ty * 4 + i) * F_OUT + n0 + tx * 4;
        *(float4*)&g_h[idx] = make_float4(acc[i][0], acc[i][1], acc[i][2], acc[i][3]);
        #pragma unroll
        for (int jp = 0; jp < 2; jp++) {
            float v0 = acc[i][2 * jp], v1 = acc[i][2 * jp + 1];
            uint32_t hp = bfpk(v0, v1);
            float r0 = v0 - __uint_as_float(hp << 16);
            float r1 = v1 - __uint_as_float(hp & 0xFFFF0000u);
            *(uint32_t*)&g_hh[idx + 2 * jp] = hp;
            *(uint32_t*)&g_hl[idx + 2 * jp] = bfpk(r0, r1);
        }
    }
}

// ---------------------------------------------------------------------------
// Kernel 2: q = h @ A (per head), scaled by log2(e), written as bf16 hi/lo.
// ---------------------------------------------------------------------------
__global__ __launch_bounds__(256) void k_gemm_hA(const float* __restrict__ A) {
    __shared__ float sH[64][65];
    __shared__ float sA[64][65];
    const int tid = threadIdx.x;
    const int ty = tid >> 4, tx = tid & 15;
    const int head = blockIdx.y;
    const int n0 = blockIdx.x * 64;

    {
        const int r  = tid >> 2;
        const int c0 = (tid & 3) * 16;
        #pragma unroll
        for (int cc = 0; cc < 16; cc += 4) {
            float4 v = *(const float4*)&g_h[(n0 + r) * F_OUT + head * DH + c0 + cc];
            sH[c0 + cc + 0][r] = v.x; sH[c0 + cc + 1][r] = v.y;
            sH[c0 + cc + 2][r] = v.z; sH[c0 + cc + 3][r] = v.w;
            float4 a = *(const float4*)&A[head * DH * DH + r * DH + c0 + cc];
            sA[r][c0 + cc + 0] = a.x; sA[r][c0 + cc + 1] = a.y;
            sA[r][c0 + cc + 2] = a.z; sA[r][c0 + cc + 3] = a.w;
        }
    }
    __syncthreads();

    float acc[4][4] = {};
    #pragma unroll 16
    for (int d = 0; d < DH; d++) {
        float a[4], b[4];
        #pragma unroll
        for (int i = 0; i < 4; i++) a[i] = sH[d][ty * 4 + i];
        #pragma unroll
        for (int j = 0; j < 4; j++) b[j] = sA[d][tx * 4 + j];
        #pragma unroll
        for (int i = 0; i < 4; i++)
            #pragma unroll
            for (int j = 0; j < 4; j++)
                acc[i][j] = fmaf(a[i], b[j], acc[i][j]);
    }
    #pragma unroll
    for (int i = 0; i < 4; i++) {
        const int idx = (n0 + ty * 4 + i) * F_OUT + head * DH + tx * 4;
        #pragma unroll
        for (int jp = 0; jp < 2; jp++) {
            float v0 = acc[i][2 * jp] * LOG2E, v1 = acc[i][2 * jp + 1] * LOG2E;
            uint32_t hp = bfpk(v0, v1);
            float r0 = v0 - __uint_as_float(hp << 16);
            float r1 = v1 - __uint_as_float(hp & 0xFFFF0000u);
            *(uint32_t*)&g_qh[idx + 2 * jp] = hp;
            *(uint32_t*)&g_ql[idx + 2 * jp] = bfpk(r0, r1);
        }
    }
}

// ---------------------------------------------------------------------------
// Kernel 3: flash attention via mma.sync; warp owns 32 q rows (2 m16 tiles)
// so every K/V B-fragment feeds 2 mmas -> half the ldsm/crossbar traffic.
// Block = 128 threads / 4 warps -> q-tile 128, grid 256.
// ---------------------------------------------------------------------------
__global__ __launch_bounds__(128, 2) void k_attn(float* __restrict__ Out) {
    __shared__ __align__(16) char smem[2 * STAGE_SZ];   // 36864 B (also Q staging)
    const uint32_t sb = smem_u32(smem);

    const int tid  = threadIdx.x;
    const int w    = tid >> 5;
    const int lane = tid & 31;
    const int head = blockIdx.y;
    const int q0   = blockIdx.x * QTILE;
    const int hb   = head * DH;

    // ldmatrix per-lane address constants
    const int lm = lane >> 3, lr = lane & 7;
    const int sKey = ((lm >> 1) << 3) + lr;   // S-B: key row offset
    const int sD   = (lm & 1) << 3;           // S-B: d col offset
    const int vKey = ((lm & 1) << 3) + lr;    // V-B(trans): key row offset
    const int vD   = (lm >> 1) << 3;          // V-B(trans): dim col offset
    const int qRow = ((lm & 1) << 3) + lr;    // Q-A: row offset within 16-row tile
    const int qCol = (lm >> 1) << 3;

    // ---- stage Q (hi at sb, lo at sb+STAGE_SZ) in the K-stage area ----
    {
        const int r = tid;                     // 0..127 -> q row
        const __nv_bfloat16* qh = &g_qh[(size_t)(q0 + r) * F_OUT + hb];
        const __nv_bfloat16* ql = &g_ql[(size_t)(q0 + r) * F_OUT + hb];
        const uint32_t d0 = sb + r * PITCH;
        #pragma unroll
        for (int c = 0; c < 8; c++) cpa16(d0 + c * 16, qh + c * 8);
        const uint32_t d1 = sb + STAGE_SZ + r * PITCH;
        #pragma unroll
        for (int c = 0; c < 8; c++) cpa16(d1 + c * 16, ql + c * 8);
    }
    CP_COMMIT();
    CP_WAIT0();
    __syncthreads();

    // Q A-fragments: [s*2+m] for k-step s (0..3), m-tile m (0..1); hi and lo
    uint32_t qa[8][4], qb[8][4];
    #pragma unroll
    for (int m = 0; m < 2; m++) {
        const uint32_t qbh = sb + (w * 32 + m * 16 + qRow) * PITCH + qCol * 2;
        const uint32_t qbl = qbh + STAGE_SZ;
        #pragma unroll
        for (int s = 0; s < 4; s++) {
            ldsm4(qbh + 16 * s * 2, qa[s * 2 + m][0], qa[s * 2 + m][1],
                                    qa[s * 2 + m][2], qa[s * 2 + m][3]);
            ldsm4(qbl + 16 * s * 2, qb[s * 2 + m][0], qb[s * 2 + m][1],
                                    qb[s * 2 + m][2], qb[s * 2 + m][3]);
        }
    }
    __syncthreads();   // Q staging area now free for K tiles

    // ---- prologue: load K tile 0 into stage 0 ----
    {
        const int r = tid >> 1, cb = (tid & 1) * 4;
        const uint32_t d0 = sb + r * PITCH + cb * 16;
        const __nv_bfloat16* kh = &g_hh[(size_t)r * F_OUT + hb];
        const __nv_bfloat16* kl = &g_hl[(size_t)r * F_OUT + hb];
        #pragma unroll
        for (int c = 0; c < 4; c++) cpa16(d0 + c * 16, kh + (cb + c) * 8);
        #pragma unroll
        for (int c = 0; c < 4; c++) cpa16(d0 + STG + c * 16, kl + (cb + c) * 8);
    }
    CP_COMMIT();

    float oc[2][8][4];
    #pragma unroll
    for (int m = 0; m < 2; m++)
        #pragma unroll
        for (int j = 0; j < 8; j++)
            #pragma unroll
            for (int k = 0; k < 4; k++) oc[m][j][k] = 0.f;
    float lsum[2][2] = {};   // [m][half]: rows g / g+8

    for (int t = 0; t < NT; t++) {
        CP_WAIT0();
        __syncthreads();
        const uint32_t stg = sb + (t & 1) * STAGE_SZ;

        // prefetch next tile into other stage
        if (t + 1 < NT) {
            const int r = tid >> 1, cb = (tid & 1) * 4;
            const uint32_t d0 = sb + ((t + 1) & 1) * STAGE_SZ + r * PITCH + cb * 16;
            const __nv_bfloat16* kh = &g_hh[(size_t)((t + 1) * KTILE + r) * F_OUT + hb];
            const __nv_bfloat16* kl = &g_hl[(size_t)((t + 1) * KTILE + r) * F_OUT + hb];
            #pragma unroll
            for (int c = 0; c < 4; c++) cpa16(d0 + c * 16, kh + (cb + c) * 8);
            #pragma unroll
            for (int c = 0; c < 4; c++) cpa16(d0 + STG + c * 16, kl + (cb + c) * 8);
        }
        CP_COMMIT();

        const uint32_t sAddr = stg + sKey * PITCH + sD * 2;
        const uint32_t vAddr = stg + vKey * PITCH + vD * 2;

        // ---- per-16-key block: S -> softmax -> PV ----
        #pragma unroll
        for (int u = 0; u < 4; u++) {
            // S = Q K^T (3-mma compensated), both m-tiles per B-fragment
            float sc[2][2][4];
            #pragma unroll
            for (int m = 0; m < 2; m++)
                #pragma unroll
                for (int k = 0; k < 4; k++) { sc[m][0][k] = 0.f; sc[m][1][k] = 0.f; }

            #pragma unroll
            for (int s = 0; s < 4; s++) {
                const uint32_t a = sAddr + (16 * u) * PITCH + (16 * s) * 2;
                uint32_t h0, h1, h2, h3, l0, l1, l2, l3;
                ldsm4(a,       h0, h1, h2, h3);
                ldsm4(a + STG, l0, l1, l2, l3);
                #pragma unroll
                for (int m = 0; m < 2; m++) {
                    mma16816(sc[m][0], qa[s * 2 + m], h0, h1);
                    mma16816(sc[m][1], qa[s * 2 + m], h2, h3);
                    mma16816(sc[m][0], qa[s * 2 + m], l0, l1);
                    mma16816(sc[m][1], qa[s * 2 + m], l2, l3);
                    mma16816(sc[m][0], qb[s * 2 + m], h0, h1);
                    mma16816(sc[m][1], qb[s * 2 + m], h2, h3);
                }
            }

            // softmax + build P hi/lo A-fragments
            uint32_t pah[2][4], pal[2][4];
            #pragma unroll
            for (int m = 0; m < 2; m++) {
                float e[8];
                #pragma unroll
                for (int k = 0; k < 4; k++) {
                    float v0 = sc[m][0][k];
                    e[k] = exp2_fast(fmaxf(v0, 0.2f * v0));
                    float v1 = sc[m][1][k];
                    e[4 + k] = exp2_fast(fmaxf(v1, 0.2f * v1));
                }
                lsum[m][0] += (e[0] + e[1]) + (e[4] + e[5]);
                lsum[m][1] += (e[2] + e[3]) + (e[6] + e[7]);

                pah[m][0] = bfpk(e[0], e[1]);
                pah[m][1] = bfpk(e[2], e[3]);
                pah[m][2] = bfpk(e[4], e[5]);
                pah[m][3] = bfpk(e[6], e[7]);
                pal[m][0] = bfpk(e[0] - __uint_as_float(pah[m][0] << 16),
                                 e[1] - __uint_as_float(pah[m][0] & 0xFFFF0000u));
                pal[m][1] = bfpk(e[2] - __uint_as_float(pah[m][1] << 16),
                                 e[3] - __uint_as_float(pah[m][1] & 0xFFFF0000u));
                pal[m][2] = bfpk(e[4] - __uint_as_float(pah[m][2] << 16),
                                 e[5] - __uint_as_float(pah[m][2] & 0xFFFF0000u));
                pal[m][3] = bfpk(e[6] - __uint_as_float(pah[m][3] << 16),
                                 e[7] - __uint_as_float(pah[m][3] & 0xFFFF0000u));
            }

            // O += P V (V = K tile, trans ldmatrix), both m-tiles per B-fragment
            #pragma unroll
            for (int d = 0; d < 4; d++) {
                const uint32_t a = vAddr + (16 * u) * PITCH + (16 * d) * 2;
                uint32_t h0, h1, h2, h3, l0, l1, l2, l3;
                ldsm4t(a,       h0, h1, h2, h3);
                ldsm4t(a + STG, l0, l1, l2, l3);
                #pragma unroll
                for (int m = 0; m < 2; m++) {
                    mma16816(oc[m][2 * d],     pah[m], h0, h1);
                    mma16816(oc[m][2 * d + 1], pah[m], h2, h3);
                    mma16816(oc[m][2 * d],     pah[m], l0, l1);
                    mma16816(oc[m][2 * d + 1], pah[m], l2, l3);
                    mma16816(oc[m][2 * d],     pal[m], h0, h1);
                    mma16816(oc[m][2 * d + 1], pal[m], h2, h3);
                }
            }
        }
    }

    // ---- reduce lsum across quad, normalize, write O ----
    const int g  = lane >> 2, tg = lane & 3;
    #pragma unroll
    for (int m = 0; m < 2; m++) {
        float lA = lsum[m][0], lB = lsum[m][1];
        lA += __shfl_xor_sync(0xffffffffu, lA, 1);
        lA += __shfl_xor_sync(0xffffffffu, lA, 2);
        lB += __shfl_xor_sync(0xffffffffu, lB, 1);
        lB += __shfl_xor_sync(0xffffffffu, lB, 2);
        const float invA = 1.0f / lA, invB = 1.0f / lB;

        const int rowA = q0 + w * 32 + m * 16 + g;
        float* outA = &Out[(size_t)rowA * F_OUT + hb + 2 * tg];
        float* outB = outA + 8 * F_OUT;
        #pragma unroll
        for (int j = 0; j < 8; j++) {
            *(float2*)(outA + 8 * j) = make_float2(oc[m][j][0] * invA, oc[m][j][1] * invA);
            *(float2*)(outB + 8 * j) = make_float2(oc[m][j][2] * invB, oc[m][j][3] * invB);
        }
    }
}

// ---------------------------------------------------------------------------
extern "C" void kernel_launch(void* const* d_in, const int* in_sizes, int n_in,
                              void* d_out, int out_size) {
    const float* x = (const float*)d_in[0];
    // d_in[1] = adj (unused by the reference forward)
    const float* W = (const float*)d_in[2];
    const float* A = (const float*)d_in[3];
    float* out = (float*)d_out;

    k_gemm_xwT<<<dim3(N_NODES / 64, F_OUT / 64), 256>>>(x, W);
    k_gemm_hA<<<dim3(N_NODES / 64, HEADS), 256>>>(A);
    k_attn<<<dim3(N_NODES / QTILE, HEADS), 128>>>(out);
}